// round 1
// baseline (speedup 1.0000x reference)
#include <cuda_runtime.h>
#include <cuda_bf16.h>

// Problem constants (fixed by the reference).
#define BB   2
#define DD   96
#define HH   96
#define WW   96
#define CIN  16
#define COUT 32
#define KK   3
#define NK   27                  // 3^3 neighbor offsets
#define GRIDVOL (BB*DD*HH*WW)    // 1,769,472 voxels
#define NWELEM (NK*CIN*COUT)     // 13,824 weights

#define CONV_BLOCKS 592          // 148 SMs * 4 blocks (55KB smem each)
#define CONV_THREADS 256         // 8 warps per block

// Scratch: voxel -> point index (-1 if empty), and swizzle-repacked weights.
__device__ int   g_grid[GRIDVOL];
__device__ float g_wsw[NWELEM];

// ---------------------------------------------------------------------------
// Scatter point ids into the index grid. Indices are unique (replace=False).
__global__ void scatter_idx_kernel(const int4* __restrict__ idx, int n) {
    int p = blockIdx.x * blockDim.x + threadIdx.x;
    if (p < n) {
        int4 q = idx[p];  // b, z, y, x
        g_grid[((q.x * DD + q.y) * HH + q.z) * WW + q.w] = p;
    }
}

// ---------------------------------------------------------------------------
// Repack conv_w [co][ci][kd][kh][kw] -> swizzled float4 layout:
//   float4 block index = (k*32 + co)*4 + (ci4 ^ ((co>>1)&3)),  lane ci&3.
// The xor swizzle makes per-lane (lane=co) LDS.128 reads conflict-free.
__global__ void repack_w_kernel(const float* __restrict__ w) {
    int t = blockIdx.x * blockDim.x + threadIdx.x;   // 27 blocks * 512 = 13824
    if (t < NWELEM) {
        int k  = t / (CIN * COUT);
        int r  = t % (CIN * COUT);
        int ci = r / COUT;
        int co = r % COUT;
        float v = w[(co * CIN + ci) * NK + k];
        int ci4 = ci >> 2, cl = ci & 3;
        int pos = ((k * COUT + co) * 4 + (ci4 ^ ((co >> 1) & 3))) * 4 + cl;
        g_wsw[pos] = v;
    }
}

// ---------------------------------------------------------------------------
// Warp-per-point sparse gather conv.
// Lane = output channel. Lanes 0..26 probe the 27 neighbor voxels, occupied
// ones are compacted with ballot/ffs; each occupied neighbor contributes
// 16 FFMAs per lane against smem weights.
__global__ __launch_bounds__(CONV_THREADS)
void conv_kernel(const float4* __restrict__ feat4,   // [n][4] float4 = 16 ch
                 const int4*   __restrict__ idx,     // [n] (b,z,y,x)
                 const float*  __restrict__ bias,    // [32]
                 float*        __restrict__ out,     // [n][32]
                 int n) {
    extern __shared__ float4 sw[];                   // 3456 float4 = 55296 B
    __shared__ float sbias[COUT];

    // Cooperative weight + bias load.
    const float4* gw4 = (const float4*)g_wsw;
    for (int i = threadIdx.x; i < NWELEM / 4; i += CONV_THREADS) sw[i] = gw4[i];
    if (threadIdx.x < COUT) sbias[threadIdx.x] = bias[threadIdx.x];
    __syncthreads();

    const int lane = threadIdx.x & 31;
    const int warp = threadIdx.x >> 5;
    const int wg   = blockIdx.x * (CONV_THREADS / 32) + warp;
    const int wstride = CONV_BLOCKS * (CONV_THREADS / 32);

    // Neighbor offset decode for this lane (valid for lane < 27).
    const int dz = lane / 9 - 1;
    const int dy = (lane / 3) % 3 - 1;
    const int dx = lane % 3 - 1;

    const float4* wbase = sw + lane * 4;
    const int s = (lane >> 1) & 3;
    const float b0 = sbias[lane];

    for (int p = wg; p < n; p += wstride) {
        int4 q = idx[p];                 // uniform load (broadcast)
        int j = -1;
        if (lane < NK) {
            int zz = q.y + dz, yy = q.z + dy, xx = q.w + dx;
            if ((unsigned)zz < (unsigned)DD &&
                (unsigned)yy < (unsigned)HH &&
                (unsigned)xx < (unsigned)WW) {
                j = __ldg(&g_grid[((q.x * DD + zz) * HH + yy) * WW + xx]);
            }
        }
        unsigned m = __ballot_sync(0xffffffffu, j >= 0);
        float acc = b0;

        while (m) {
            int k = __ffs(m) - 1;
            m &= m - 1;
            int jj = __shfl_sync(0xffffffffu, j, k);

            const float4* fp = feat4 + ((long)jj << 2);
            float4 f0 = fp[0], f1 = fp[1], f2 = fp[2], f3 = fp[3];

            const float4* wp = wbase + (k << 7);     // k * 32co * 4
            float4 w0 = wp[0 ^ s];
            float4 w1 = wp[1 ^ s];
            float4 w2 = wp[2 ^ s];
            float4 w3 = wp[3 ^ s];

            acc += f0.x * w0.x; acc += f0.y * w0.y;
            acc += f0.z * w0.z; acc += f0.w * w0.w;
            acc += f1.x * w1.x; acc += f1.y * w1.y;
            acc += f1.z * w1.z; acc += f1.w * w1.w;
            acc += f2.x * w2.x; acc += f2.y * w2.y;
            acc += f2.z * w2.z; acc += f2.w * w2.w;
            acc += f3.x * w3.x; acc += f3.y * w3.y;
            acc += f3.z * w3.z; acc += f3.w * w3.w;
        }
        out[(long)p * COUT + lane] = acc;
    }
}

// ---------------------------------------------------------------------------
extern "C" void kernel_launch(void* const* d_in, const int* in_sizes, int n_in,
                              void* d_out, int out_size) {
    const float* feat = (const float*)d_in[0];   // [n,16] f32
    const int*   idx  = (const int*)d_in[1];     // [n,4]  i32
    const float* w    = (const float*)d_in[2];   // [32,16,3,3,3] f32
    const float* bias = (const float*)d_in[3];   // [32] f32
    int n = in_sizes[1] / 4;

    void* gptr = nullptr;
    cudaGetSymbolAddress(&gptr, g_grid);
    cudaMemsetAsync(gptr, 0xFF, sizeof(int) * (size_t)GRIDVOL);

    scatter_idx_kernel<<<(n + 255) / 256, 256>>>((const int4*)idx, n);
    repack_w_kernel<<<NK, 512>>>(w);

    cudaFuncSetAttribute(conv_kernel,
                         cudaFuncAttributeMaxDynamicSharedMemorySize,
                         (NWELEM / 4) * (int)sizeof(float4));
    conv_kernel<<<CONV_BLOCKS, CONV_THREADS, (NWELEM / 4) * sizeof(float4)>>>(
        (const float4*)feat, (const int4*)idx, bias, (float*)d_out, n);
}

// round 2
// speedup vs baseline: 1.3787x; 1.3787x over previous
#include <cuda_runtime.h>
#include <cuda_bf16.h>

// Problem constants (fixed by the reference).
#define BB   2
#define DD   96
#define HH   96
#define WW   96
#define CIN  16
#define COUT 32
#define NK   27
#define GRIDVOL (BB*DD*HH*WW)      // 1,769,472
#define NWELEM (NK*CIN*COUT)       // 13,824

#define NBIN  26                   // 27 offsets minus the center (k=13)
#define NCAP  262144               // capacity per bin (>= max pairs per k)
#define CHUNK 64                   // points per block in probe kernel

#define CONV_BLOCKS  592           // 148 SMs * 4
#define CONV_THREADS 256
#define TOTW (CONV_BLOCKS*(CONV_THREADS/32))   // 4736 warps

// Scratch (static __device__ arrays: allocation-free).
__device__ int   g_grid[GRIDVOL];              // voxel -> point id, -1 empty
__device__ float g_wk[NWELEM];                 // [k][ci][co]
__device__ int   g_cnt[NBIN];                  // pairs per bin
__device__ int2  g_pairs[(long)NBIN * NCAP];   // (in_idx, out_idx) per bin

// ---------------------------------------------------------------------------
__global__ void scatter_idx_kernel(const int4* __restrict__ idx, int n) {
    int p = blockIdx.x * blockDim.x + threadIdx.x;
    if (p < n) {
        int4 q = idx[p];  // b, z, y, x
        g_grid[((q.x * DD + q.y) * HH + q.z) * WW + q.w] = p;
    }
}

// conv_w [co][ci][kd][kh][kw] -> g_wk[k][ci][co]
__global__ void repack_w_kernel(const float* __restrict__ w) {
    int t = blockIdx.x * blockDim.x + threadIdx.x;
    if (t < NWELEM) {
        int k  = t / (CIN * COUT);
        int r  = t % (CIN * COUT);
        int ci = r / COUT;
        int co = r % COUT;
        g_wk[(k * CIN + ci) * COUT + co] = w[(co * CIN + ci) * NK + k];
    }
}

// ---------------------------------------------------------------------------
// Build 26 pair lists. Warp handles 8 points; lane l (<26) probes offset
// kk = l<13 ? l : l+1 (center skipped). Hits staged in smem, flushed with one
// aggregated global atomic per bin per block.
__global__ __launch_bounds__(256)
void probe_kernel(const int4* __restrict__ idx, int n) {
    __shared__ int  scnt[NBIN];
    __shared__ int  sbase[NBIN];
    __shared__ int2 srec[NBIN * CHUNK];

    int tid = threadIdx.x, lane = tid & 31, warp = tid >> 5;
    if (tid < NBIN) scnt[tid] = 0;
    __syncthreads();

    int kk = lane < 13 ? lane : lane + 1;
    int dz = kk / 9 - 1, dy = (kk / 3) % 3 - 1, dx = kk % 3 - 1;
    int p0 = blockIdx.x * CHUNK + warp * (CHUNK / 8);

#pragma unroll
    for (int r = 0; r < CHUNK / 8; r++) {
        int p = p0 + r;
        if (p < n && lane < NBIN) {
            int4 q = __ldg(&idx[p]);      // broadcast
            int zz = q.y + dz, yy = q.z + dy, xx = q.w + dx;
            if ((unsigned)zz < (unsigned)DD &&
                (unsigned)yy < (unsigned)HH &&
                (unsigned)xx < (unsigned)WW) {
                int j = __ldg(&g_grid[((q.x * DD + zz) * HH + yy) * WW + xx]);
                if (j >= 0) {
                    int pos = atomicAdd(&scnt[lane], 1);
                    srec[lane * CHUNK + pos] = make_int2(j, p);
                }
            }
        }
    }
    __syncthreads();
    if (tid < NBIN) sbase[tid] = atomicAdd(&g_cnt[tid], scnt[tid]);
    __syncthreads();
    for (int t = tid; t < NBIN * CHUNK; t += 256) {
        int b = t / CHUNK, i = t % CHUNK;
        if (i < scnt[b]) g_pairs[(long)b * NCAP + sbase[b] + i] = srec[t];
    }
}

// ---------------------------------------------------------------------------
__device__ __forceinline__ float dot16(const float4& f0, const float4& f1,
                                       const float4& f2, const float4& f3,
                                       const float* wk) {
    float a = f0.x * wk[0] + f0.y * wk[1];
    float b = f0.z * wk[2] + f0.w * wk[3];
    a += f1.x * wk[4]; b += f1.y * wk[5];
    a += f1.z * wk[6]; b += f1.w * wk[7];
    a += f2.x * wk[8]; b += f2.y * wk[9];
    a += f2.z * wk[10]; b += f2.w * wk[11];
    a += f3.x * wk[12]; b += f3.y * wk[13];
    a += f3.z * wk[14]; b += f3.w * wk[15];
    return a + b;
}

// Center tap + bias: initializes out[p][co] (covers whole output).
__global__ __launch_bounds__(256)
void center_kernel(const float4* __restrict__ feat4,
                   const float* __restrict__ bias,
                   float* __restrict__ out, int n) {
    int lane = threadIdx.x & 31;
    int w = blockIdx.x * (CONV_THREADS / 32) + (threadIdx.x >> 5);
    float wk[CIN];
#pragma unroll
    for (int ci = 0; ci < CIN; ci++)
        wk[ci] = g_wk[(13 * CIN + ci) * COUT + lane];
    float b0 = __ldg(&bias[lane]);
    for (int p = w; p < n; p += TOTW) {
        const float4* fp = feat4 + ((long)p << 2);
        float4 f0 = __ldg(fp), f1 = __ldg(fp + 1),
               f2 = __ldg(fp + 2), f3 = __ldg(fp + 3);
        out[(long)p * COUT + lane] = b0 + dot16(f0, f1, f2, f3, wk);
    }
}

// Pair conv: warp pinned to one bin (one kernel offset); W_k in registers.
__global__ __launch_bounds__(256)
void pair_conv_kernel(const float4* __restrict__ feat4,
                      float* __restrict__ out) {
    int lane = threadIdx.x & 31;
    int w = blockIdx.x * (CONV_THREADS / 32) + (threadIdx.x >> 5);
    int b = w % NBIN, slice = w / NBIN;
    int nwk = (TOTW - b + NBIN - 1) / NBIN;    // warps serving bin b
    int kk = b < 13 ? b : b + 1;

    float wk[CIN];
#pragma unroll
    for (int ci = 0; ci < CIN; ci++)
        wk[ci] = g_wk[(kk * CIN + ci) * COUT + lane];

    int cnt = g_cnt[b];
    const int2* pr = g_pairs + (long)b * NCAP;
    int chunk = (cnt + nwk - 1) / nwk;
    int i0 = slice * chunk;
    int i1 = min(cnt, i0 + chunk);

    int i = i0;
    for (; i + 1 < i1; i += 2) {
        int2 r0 = __ldg(&pr[i]);
        int2 r1 = __ldg(&pr[i + 1]);
        const float4* fa = feat4 + ((long)r0.x << 2);
        const float4* fb = feat4 + ((long)r1.x << 2);
        float4 a0 = __ldg(fa), a1 = __ldg(fa + 1),
               a2 = __ldg(fa + 2), a3 = __ldg(fa + 3);
        float4 c0 = __ldg(fb), c1 = __ldg(fb + 1),
               c2 = __ldg(fb + 2), c3 = __ldg(fb + 3);
        float s0 = dot16(a0, a1, a2, a3, wk);
        float s1 = dot16(c0, c1, c2, c3, wk);
        atomicAdd(&out[(long)r0.y * COUT + lane], s0);
        atomicAdd(&out[(long)r1.y * COUT + lane], s1);
    }
    if (i < i1) {
        int2 r0 = __ldg(&pr[i]);
        const float4* fa = feat4 + ((long)r0.x << 2);
        float4 a0 = __ldg(fa), a1 = __ldg(fa + 1),
               a2 = __ldg(fa + 2), a3 = __ldg(fa + 3);
        atomicAdd(&out[(long)r0.y * COUT + lane], dot16(a0, a1, a2, a3, wk));
    }
}

// ---------------------------------------------------------------------------
extern "C" void kernel_launch(void* const* d_in, const int* in_sizes, int n_in,
                              void* d_out, int out_size) {
    const float* feat = (const float*)d_in[0];   // [n,16] f32
    const int*   idx  = (const int*)d_in[1];     // [n,4]  i32
    const float* w    = (const float*)d_in[2];   // [32,16,3,3,3] f32
    const float* bias = (const float*)d_in[3];   // [32] f32
    int n = in_sizes[1] / 4;

    void* gptr = nullptr; cudaGetSymbolAddress(&gptr, g_grid);
    void* cptr = nullptr; cudaGetSymbolAddress(&cptr, g_cnt);
    cudaMemsetAsync(gptr, 0xFF, sizeof(int) * (size_t)GRIDVOL);
    cudaMemsetAsync(cptr, 0, sizeof(int) * NBIN);

    scatter_idx_kernel<<<(n + 255) / 256, 256>>>((const int4*)idx, n);
    repack_w_kernel<<<NK, 512>>>(w);
    probe_kernel<<<(n + CHUNK - 1) / CHUNK, 256>>>((const int4*)idx, n);
    center_kernel<<<CONV_BLOCKS, CONV_THREADS>>>(
        (const float4*)feat, bias, (float*)d_out, n);
    pair_conv_kernel<<<CONV_BLOCKS, CONV_THREADS>>>(
        (const float4*)feat, (float*)d_out);
}

// round 3
// speedup vs baseline: 1.4155x; 1.0267x over previous
#include <cuda_runtime.h>
#include <cuda_bf16.h>

// Problem constants (fixed by the reference).
#define BB   2
#define DD   96
#define HH   96
#define WW   96
#define CIN  16
#define COUT 32
#define NK   27
#define GRIDVOL (BB*DD*HH*WW)      // 1,769,472
#define NWELEM (NK*CIN*COUT)       // 13,824

#define NBIN  26                   // 27 offsets minus the center (k=13)
#define NCAP  262144
#define CHUNK 64

#define CONV_BLOCKS  592
#define CONV_THREADS 256
#define TOTW (CONV_BLOCKS*(CONV_THREADS/32))   // 4736 warps

typedef unsigned long long u64;

// Scratch (static __device__ arrays: allocation-free).
__device__ int  g_grid[GRIDVOL];               // voxel -> point id, -1 empty
__device__ u64  g_wk2[NK * (CIN/2) * COUT];    // [k][ci2][co] packed f32x2
__device__ int  g_cnt[NBIN];
__device__ int2 g_pairs[(long)NBIN * NCAP];

// ---------------------------------------------------------------------------
// Packed f32x2 helpers (sm_103a FFMA2 path).
__device__ __forceinline__ u64 fma2(u64 a, u64 b, u64 c) {
    u64 d; asm("fma.rn.f32x2 %0, %1, %2, %3;" : "=l"(d) : "l"(a), "l"(b), "l"(c));
    return d;
}
__device__ __forceinline__ u64 mul2(u64 a, u64 b) {
    u64 d; asm("mul.rn.f32x2 %0, %1, %2;" : "=l"(d) : "l"(a), "l"(b));
    return d;
}
__device__ __forceinline__ u64 add2(u64 a, u64 b) {
    u64 d; asm("add.rn.f32x2 %0, %1, %2;" : "=l"(d) : "l"(a), "l"(b));
    return d;
}
__device__ __forceinline__ float hsum2(u64 a) {
    unsigned lo, hi;
    asm("mov.b64 {%0, %1}, %2;" : "=r"(lo), "=r"(hi) : "l"(a));
    return __uint_as_float(lo) + __uint_as_float(hi);
}

// 16-channel dot product, packed: f = 4 x ulonglong2 (16 floats), w = 8 x u64.
__device__ __forceinline__ float dot16p(const ulonglong2& f0, const ulonglong2& f1,
                                        const ulonglong2& f2, const ulonglong2& f3,
                                        const u64* w) {
    u64 s0 = mul2(f0.x, w[0]);
    u64 s1 = mul2(f0.y, w[1]);
    s0 = fma2(f1.x, w[2], s0);
    s1 = fma2(f1.y, w[3], s1);
    s0 = fma2(f2.x, w[4], s0);
    s1 = fma2(f2.y, w[5], s1);
    s0 = fma2(f3.x, w[6], s0);
    s1 = fma2(f3.y, w[7], s1);
    return hsum2(add2(s0, s1));
}

// ---------------------------------------------------------------------------
__global__ void scatter_idx_kernel(const int4* __restrict__ idx, int n) {
    int p = blockIdx.x * blockDim.x + threadIdx.x;
    if (p < n) {
        int4 q = idx[p];  // b, z, y, x
        g_grid[((q.x * DD + q.y) * HH + q.z) * WW + q.w] = p;
    }
}

// conv_w [co][ci][kd][kh][kw] -> g_wk2[k][ci/2][co] (f32x2 packed over ci).
__global__ void repack_w_kernel(const float* __restrict__ w) {
    int t = blockIdx.x * blockDim.x + threadIdx.x;   // NK*8*COUT = 6912
    if (t < NK * (CIN/2) * COUT) {
        int k   = t / ((CIN/2) * COUT);
        int r   = t % ((CIN/2) * COUT);
        int ci2 = r / COUT;
        int co  = r % COUT;
        float w0 = w[(co * CIN + 2*ci2    ) * NK + k];
        float w1 = w[(co * CIN + 2*ci2 + 1) * NK + k];
        g_wk2[t] = ((u64)__float_as_uint(w1) << 32) | __float_as_uint(w0);
    }
}

// ---------------------------------------------------------------------------
// Build 26 pair lists (smem staging, one aggregated global atomic per bin).
__global__ __launch_bounds__(256)
void probe_kernel(const int4* __restrict__ idx, int n) {
    __shared__ int  scnt[NBIN];
    __shared__ int  sbase[NBIN];
    __shared__ int2 srec[NBIN * CHUNK];

    int tid = threadIdx.x, lane = tid & 31, warp = tid >> 5;
    if (tid < NBIN) scnt[tid] = 0;
    __syncthreads();

    int kk = lane < 13 ? lane : lane + 1;
    int dz = kk / 9 - 1, dy = (kk / 3) % 3 - 1, dx = kk % 3 - 1;
    int p0 = blockIdx.x * CHUNK + warp * (CHUNK / 8);

#pragma unroll
    for (int r = 0; r < CHUNK / 8; r++) {
        int p = p0 + r;
        if (p < n && lane < NBIN) {
            int4 q = __ldg(&idx[p]);
            int zz = q.y + dz, yy = q.z + dy, xx = q.w + dx;
            if ((unsigned)zz < (unsigned)DD &&
                (unsigned)yy < (unsigned)HH &&
                (unsigned)xx < (unsigned)WW) {
                int j = __ldg(&g_grid[((q.x * DD + zz) * HH + yy) * WW + xx]);
                if (j >= 0) {
                    int pos = atomicAdd(&scnt[lane], 1);
                    srec[lane * CHUNK + pos] = make_int2(j, p);
                }
            }
        }
    }
    __syncthreads();
    if (tid < NBIN) sbase[tid] = atomicAdd(&g_cnt[tid], scnt[tid]);
    __syncthreads();
    for (int t = tid; t < NBIN * CHUNK; t += 256) {
        int b = t / CHUNK, i = t % CHUNK;
        if (i < scnt[b]) g_pairs[(long)b * NCAP + sbase[b] + i] = srec[t];
    }
}

// ---------------------------------------------------------------------------
// Center tap + bias: initializes out. 2 points per iteration for MLP.
__global__ __launch_bounds__(256)
void center_kernel(const ulonglong2* __restrict__ feat2,   // [n][4] (64B/row)
                   const float* __restrict__ bias,
                   float* __restrict__ out, int n) {
    int lane = threadIdx.x & 31;
    int w = blockIdx.x * (CONV_THREADS / 32) + (threadIdx.x >> 5);
    u64 wk[8];
#pragma unroll
    for (int i = 0; i < 8; i++) wk[i] = g_wk2[(13 * 8 + i) * COUT + lane];
    float b0 = __ldg(&bias[lane]);

    int p = w * 2;
    int stride = TOTW * 2;
    for (; p + 1 < n; p += stride) {
        const ulonglong2* fa = feat2 + ((long)p << 2);
        const ulonglong2* fb = fa + 4;
        ulonglong2 a0 = __ldg(fa),     a1 = __ldg(fa + 1),
                   a2 = __ldg(fa + 2), a3 = __ldg(fa + 3);
        ulonglong2 c0 = __ldg(fb),     c1 = __ldg(fb + 1),
                   c2 = __ldg(fb + 2), c3 = __ldg(fb + 3);
        out[(long)p * COUT + lane]       = b0 + dot16p(a0, a1, a2, a3, wk);
        out[(long)(p + 1) * COUT + lane] = b0 + dot16p(c0, c1, c2, c3, wk);
    }
    if (p < n) {
        const ulonglong2* fa = feat2 + ((long)p << 2);
        ulonglong2 a0 = __ldg(fa),     a1 = __ldg(fa + 1),
                   a2 = __ldg(fa + 2), a3 = __ldg(fa + 3);
        out[(long)p * COUT + lane] = b0 + dot16p(a0, a1, a2, a3, wk);
    }
}

// Pair conv: warp pinned to one bin; W_k packed in registers.
__global__ __launch_bounds__(256)
void pair_conv_kernel(const ulonglong2* __restrict__ feat2,
                      float* __restrict__ out) {
    int lane = threadIdx.x & 31;
    int w = blockIdx.x * (CONV_THREADS / 32) + (threadIdx.x >> 5);
    int b = w % NBIN, slice = w / NBIN;
    int nwk = (TOTW - b + NBIN - 1) / NBIN;
    int kk = b < 13 ? b : b + 1;

    u64 wk[8];
#pragma unroll
    for (int i = 0; i < 8; i++) wk[i] = g_wk2[(kk * 8 + i) * COUT + lane];

    int cnt = g_cnt[b];
    const int2* pr = g_pairs + (long)b * NCAP;
    int chunk = (cnt + nwk - 1) / nwk;
    int i0 = slice * chunk;
    int i1 = min(cnt, i0 + chunk);

    int i = i0;
    for (; i + 1 < i1; i += 2) {
        int2 r0 = __ldg(&pr[i]);
        int2 r1 = __ldg(&pr[i + 1]);
        const ulonglong2* fa = feat2 + ((long)r0.x << 2);
        const ulonglong2* fb = feat2 + ((long)r1.x << 2);
        ulonglong2 a0 = __ldg(fa),     a1 = __ldg(fa + 1),
                   a2 = __ldg(fa + 2), a3 = __ldg(fa + 3);
        ulonglong2 c0 = __ldg(fb),     c1 = __ldg(fb + 1),
                   c2 = __ldg(fb + 2), c3 = __ldg(fb + 3);
        float s0 = dot16p(a0, a1, a2, a3, wk);
        float s1 = dot16p(c0, c1, c2, c3, wk);
        atomicAdd(&out[(long)r0.y * COUT + lane], s0);
        atomicAdd(&out[(long)r1.y * COUT + lane], s1);
    }
    if (i < i1) {
        int2 r0 = __ldg(&pr[i]);
        const ulonglong2* fa = feat2 + ((long)r0.x << 2);
        ulonglong2 a0 = __ldg(fa),     a1 = __ldg(fa + 1),
                   a2 = __ldg(fa + 2), a3 = __ldg(fa + 3);
        atomicAdd(&out[(long)r0.y * COUT + lane], dot16p(a0, a1, a2, a3, wk));
    }
}

// ---------------------------------------------------------------------------
extern "C" void kernel_launch(void* const* d_in, const int* in_sizes, int n_in,
                              void* d_out, int out_size) {
    const float* feat = (const float*)d_in[0];   // [n,16] f32
    const int*   idx  = (const int*)d_in[1];     // [n,4]  i32
    const float* w    = (const float*)d_in[2];   // [32,16,3,3,3] f32
    const float* bias = (const float*)d_in[3];   // [32] f32
    int n = in_sizes[1] / 4;

    void* gptr = nullptr; cudaGetSymbolAddress(&gptr, g_grid);
    void* cptr = nullptr; cudaGetSymbolAddress(&cptr, g_cnt);
    cudaMemsetAsync(gptr, 0xFF, sizeof(int) * (size_t)GRIDVOL);
    cudaMemsetAsync(cptr, 0, sizeof(int) * NBIN);

    scatter_idx_kernel<<<(n + 255) / 256, 256>>>((const int4*)idx, n);
    repack_w_kernel<<<(NK * (CIN/2) * COUT + 255) / 256, 256>>>(w);
    probe_kernel<<<(n + CHUNK - 1) / CHUNK, 256>>>((const int4*)idx, n);
    center_kernel<<<CONV_BLOCKS, CONV_THREADS>>>(
        (const ulonglong2*)feat, bias, (float*)d_out, n);
    pair_conv_kernel<<<CONV_BLOCKS, CONV_THREADS>>>(
        (const ulonglong2*)feat, (float*)d_out);
}

// round 4
// speedup vs baseline: 1.5000x; 1.0597x over previous
#include <cuda_runtime.h>
#include <cuda_bf16.h>

// Problem constants (fixed by the reference).
#define BB   2
#define DD   96
#define HH   96
#define WW   96
#define CIN  16
#define COUT 32
#define NK   27
#define GRIDVOL (BB*DD*HH*WW)      // 1,769,472
#define NWELEM (NK*CIN*COUT)       // 13,824

#define NBIN  26                   // 27 offsets minus the center (k=13)
#define NCAP  262144
#define CHUNK 64

#define CONV_BLOCKS  592
#define CONV_THREADS 256
#define TOTW (CONV_BLOCKS*(CONV_THREADS/32))   // 4736 warps

typedef unsigned long long u64;

// Scratch (static __device__ arrays: allocation-free).
__device__ int  g_grid[GRIDVOL];               // voxel -> point id, -1 empty
__device__ u64  g_wk2[NK * (CIN/2) * COUT];    // [k][ci2][co] packed f32x2
__device__ int  g_cnt[NBIN];
__device__ int2 g_pairs[(long)NBIN * NCAP];

// ---------------------------------------------------------------------------
// Packed f32x2 helpers (sm_103a FFMA2 path).
__device__ __forceinline__ u64 fma2(u64 a, u64 b, u64 c) {
    u64 d; asm("fma.rn.f32x2 %0, %1, %2, %3;" : "=l"(d) : "l"(a), "l"(b), "l"(c));
    return d;
}
__device__ __forceinline__ u64 mul2(u64 a, u64 b) {
    u64 d; asm("mul.rn.f32x2 %0, %1, %2;" : "=l"(d) : "l"(a), "l"(b));
    return d;
}
__device__ __forceinline__ u64 add2(u64 a, u64 b) {
    u64 d; asm("add.rn.f32x2 %0, %1, %2;" : "=l"(d) : "l"(a), "l"(b));
    return d;
}
__device__ __forceinline__ float hsum2(u64 a) {
    unsigned lo, hi;
    asm("mov.b64 {%0, %1}, %2;" : "=r"(lo), "=r"(hi) : "l"(a));
    return __uint_as_float(lo) + __uint_as_float(hi);
}

// 16-channel dot product, packed: f = 4 x ulonglong2, w = 8 x u64.
__device__ __forceinline__ float dot16p(const ulonglong2& f0, const ulonglong2& f1,
                                        const ulonglong2& f2, const ulonglong2& f3,
                                        const u64* w) {
    u64 s0 = mul2(f0.x, w[0]);
    u64 s1 = mul2(f0.y, w[1]);
    s0 = fma2(f1.x, w[2], s0);
    s1 = fma2(f1.y, w[3], s1);
    s0 = fma2(f2.x, w[4], s0);
    s1 = fma2(f2.y, w[5], s1);
    s0 = fma2(f3.x, w[6], s0);
    s1 = fma2(f3.y, w[7], s1);
    return hsum2(add2(s0, s1));
}

// ---------------------------------------------------------------------------
__global__ void scatter_idx_kernel(const int4* __restrict__ idx, int n) {
    int p = blockIdx.x * blockDim.x + threadIdx.x;
    if (p < n) {
        int4 q = idx[p];  // b, z, y, x
        g_grid[((q.x * DD + q.y) * HH + q.z) * WW + q.w] = p;
    }
}

// conv_w [co][ci][kd][kh][kw] -> g_wk2[k][ci/2][co]; also zeroes bin counters.
__global__ void repack_w_kernel(const float* __restrict__ w) {
    int t = blockIdx.x * blockDim.x + threadIdx.x;
    if (blockIdx.x == 0 && threadIdx.x < NBIN) g_cnt[threadIdx.x] = 0;
    if (t < NK * (CIN/2) * COUT) {
        int k   = t / ((CIN/2) * COUT);
        int r   = t % ((CIN/2) * COUT);
        int ci2 = r / COUT;
        int co  = r % COUT;
        float w0 = w[(co * CIN + 2*ci2    ) * NK + k];
        float w1 = w[(co * CIN + 2*ci2 + 1) * NK + k];
        g_wk2[t] = ((u64)__float_as_uint(w1) << 32) | __float_as_uint(w0);
    }
}

// ---------------------------------------------------------------------------
// Build 26 pair lists (smem staging, one aggregated global atomic per bin).
__global__ __launch_bounds__(256)
void probe_kernel(const int4* __restrict__ idx, int n) {
    __shared__ int  scnt[NBIN];
    __shared__ int  sbase[NBIN];
    __shared__ int2 srec[NBIN * CHUNK];

    int tid = threadIdx.x, lane = tid & 31, warp = tid >> 5;
    if (tid < NBIN) scnt[tid] = 0;
    __syncthreads();

    int kk = lane < 13 ? lane : lane + 1;
    int dz = kk / 9 - 1, dy = (kk / 3) % 3 - 1, dx = kk % 3 - 1;
    int p0 = blockIdx.x * CHUNK + warp * (CHUNK / 8);

#pragma unroll
    for (int r = 0; r < CHUNK / 8; r++) {
        int p = p0 + r;
        if (p < n && lane < NBIN) {
            int4 q = __ldg(&idx[p]);
            int zz = q.y + dz, yy = q.z + dy, xx = q.w + dx;
            if ((unsigned)zz < (unsigned)DD &&
                (unsigned)yy < (unsigned)HH &&
                (unsigned)xx < (unsigned)WW) {
                int j = __ldg(&g_grid[((q.x * DD + zz) * HH + yy) * WW + xx]);
                if (j >= 0) {
                    int pos = atomicAdd(&scnt[lane], 1);
                    srec[lane * CHUNK + pos] = make_int2(j, p);
                }
            }
        }
    }
    __syncthreads();
    if (tid < NBIN) sbase[tid] = atomicAdd(&g_cnt[tid], scnt[tid]);
    __syncthreads();
    for (int t = tid; t < NBIN * CHUNK; t += 256) {
        int b = t / CHUNK, i = t % CHUNK;
        if (i < scnt[b]) g_pairs[(long)b * NCAP + sbase[b] + i] = srec[t];
    }
}

// ---------------------------------------------------------------------------
// Center tap + bias: initializes out. 4 points per iteration (16 LDG in flight).
__global__ __launch_bounds__(256)
void center_kernel(const ulonglong2* __restrict__ feat2,   // [n][4] (64B/row)
                   const float* __restrict__ bias,
                   float* __restrict__ out, int n) {
    int lane = threadIdx.x & 31;
    int w = blockIdx.x * (CONV_THREADS / 32) + (threadIdx.x >> 5);
    u64 wk[8];
#pragma unroll
    for (int i = 0; i < 8; i++) wk[i] = g_wk2[(13 * 8 + i) * COUT + lane];
    float b0 = __ldg(&bias[lane]);

    int p = w * 4;
    const int stride = TOTW * 4;
    for (; p + 3 < n; p += stride) {
        const ulonglong2* f = feat2 + ((long)p << 2);
        ulonglong2 a0 = __ldg(f),      a1 = __ldg(f + 1),
                   a2 = __ldg(f + 2),  a3 = __ldg(f + 3);
        ulonglong2 e0 = __ldg(f + 4),  e1 = __ldg(f + 5),
                   e2 = __ldg(f + 6),  e3 = __ldg(f + 7);
        ulonglong2 c0 = __ldg(f + 8),  c1 = __ldg(f + 9),
                   c2 = __ldg(f + 10), c3 = __ldg(f + 11);
        ulonglong2 g0 = __ldg(f + 12), g1 = __ldg(f + 13),
                   g2 = __ldg(f + 14), g3 = __ldg(f + 15);
        out[(long)p * COUT + lane]       = b0 + dot16p(a0, a1, a2, a3, wk);
        out[(long)(p + 1) * COUT + lane] = b0 + dot16p(e0, e1, e2, e3, wk);
        out[(long)(p + 2) * COUT + lane] = b0 + dot16p(c0, c1, c2, c3, wk);
        out[(long)(p + 3) * COUT + lane] = b0 + dot16p(g0, g1, g2, g3, wk);
    }
    for (int q = p; q < n && q < p + 4; q++) {
        const ulonglong2* f = feat2 + ((long)q << 2);
        ulonglong2 a0 = __ldg(f),     a1 = __ldg(f + 1),
                   a2 = __ldg(f + 2), a3 = __ldg(f + 3);
        out[(long)q * COUT + lane] = b0 + dot16p(a0, a1, a2, a3, wk);
    }
}

// Pair conv: warp pinned to one bin; W_k packed in registers; unroll x4.
__global__ __launch_bounds__(256)
void pair_conv_kernel(const ulonglong2* __restrict__ feat2,
                      float* __restrict__ out) {
    int lane = threadIdx.x & 31;
    int w = blockIdx.x * (CONV_THREADS / 32) + (threadIdx.x >> 5);
    int b = w % NBIN, slice = w / NBIN;
    int nwk = (TOTW - b + NBIN - 1) / NBIN;
    int kk = b < 13 ? b : b + 1;

    u64 wk[8];
#pragma unroll
    for (int i = 0; i < 8; i++) wk[i] = g_wk2[(kk * 8 + i) * COUT + lane];

    int cnt = g_cnt[b];
    const int2* pr = g_pairs + (long)b * NCAP;
    int chunk = (cnt + nwk - 1) / nwk;
    int i0 = slice * chunk;
    int i1 = min(cnt, i0 + chunk);

    int i = i0;
    for (; i + 3 < i1; i += 4) {
        int2 r0 = __ldg(&pr[i]);
        int2 r1 = __ldg(&pr[i + 1]);
        int2 r2 = __ldg(&pr[i + 2]);
        int2 r3 = __ldg(&pr[i + 3]);
        const ulonglong2* fa = feat2 + ((long)r0.x << 2);
        const ulonglong2* fb = feat2 + ((long)r1.x << 2);
        const ulonglong2* fc = feat2 + ((long)r2.x << 2);
        const ulonglong2* fd = feat2 + ((long)r3.x << 2);
        ulonglong2 a0 = __ldg(fa), a1 = __ldg(fa + 1),
                   a2 = __ldg(fa + 2), a3 = __ldg(fa + 3);
        ulonglong2 e0 = __ldg(fb), e1 = __ldg(fb + 1),
                   e2 = __ldg(fb + 2), e3 = __ldg(fb + 3);
        ulonglong2 c0 = __ldg(fc), c1 = __ldg(fc + 1),
                   c2 = __ldg(fc + 2), c3 = __ldg(fc + 3);
        ulonglong2 g0 = __ldg(fd), g1 = __ldg(fd + 1),
                   g2 = __ldg(fd + 2), g3 = __ldg(fd + 3);
        float s0 = dot16p(a0, a1, a2, a3, wk);
        float s1 = dot16p(e0, e1, e2, e3, wk);
        float s2 = dot16p(c0, c1, c2, c3, wk);
        float s3 = dot16p(g0, g1, g2, g3, wk);
        atomicAdd(&out[(long)r0.y * COUT + lane], s0);
        atomicAdd(&out[(long)r1.y * COUT + lane], s1);
        atomicAdd(&out[(long)r2.y * COUT + lane], s2);
        atomicAdd(&out[(long)r3.y * COUT + lane], s3);
    }
    for (; i < i1; i++) {
        int2 r0 = __ldg(&pr[i]);
        const ulonglong2* fa = feat2 + ((long)r0.x << 2);
        ulonglong2 a0 = __ldg(fa), a1 = __ldg(fa + 1),
                   a2 = __ldg(fa + 2), a3 = __ldg(fa + 3);
        atomicAdd(&out[(long)r0.y * COUT + lane], dot16p(a0, a1, a2, a3, wk));
    }
}

// ---------------------------------------------------------------------------
extern "C" void kernel_launch(void* const* d_in, const int* in_sizes, int n_in,
                              void* d_out, int out_size) {
    const float* feat = (const float*)d_in[0];   // [n,16] f32
    const int*   idx  = (const int*)d_in[1];     // [n,4]  i32
    const float* w    = (const float*)d_in[2];   // [32,16,3,3,3] f32
    const float* bias = (const float*)d_in[3];   // [32] f32
    int n = in_sizes[1] / 4;

    void* gptr = nullptr; cudaGetSymbolAddress(&gptr, g_grid);
    cudaMemsetAsync(gptr, 0xFF, sizeof(int) * (size_t)GRIDVOL);          // launch 1

    scatter_idx_kernel<<<(n + 255) / 256, 256>>>((const int4*)idx, n);   // launch 2
    repack_w_kernel<<<(NK * (CIN/2) * COUT + 255) / 256, 256>>>(w);      // launch 3
    probe_kernel<<<(n + CHUNK - 1) / CHUNK, 256>>>((const int4*)idx, n); // launch 4
    center_kernel<<<CONV_BLOCKS, CONV_THREADS>>>(
        (const ulonglong2*)feat, bias, (float*)d_out, n);                // launch 5
    pair_conv_kernel<<<CONV_BLOCKS, CONV_THREADS>>>(
        (const ulonglong2*)feat, (float*)d_out);                         // launch 6 (profiled)
}